// round 2
// baseline (speedup 1.0000x reference)
#include <cuda_runtime.h>

#define NCAP 100000
typedef unsigned long long u64;

// per-node precomputed partials of eu_w1 (src-half / dst-half)
__device__ float g_pre_a[(size_t)NCAP * 128];
__device__ float g_pre_b[(size_t)NCAP * 128];

__device__ __forceinline__ u64 pack2(float lo, float hi) {
    u64 r; asm("mov.b64 %0,{%1,%2};" : "=l"(r) : "f"(lo), "f"(hi)); return r;
}
__device__ __forceinline__ float2 unpack2(u64 v) {
    float2 f; asm("mov.b64 {%0,%1},%2;" : "=f"(f.x), "=f"(f.y) : "l"(v)); return f;
}
__device__ __forceinline__ u64 ffma2(u64 a, u64 b, u64 c) {
    u64 d; asm("fma.rn.f32x2 %0,%1,%2,%3;" : "=l"(d) : "l"(a), "l"(b), "l"(c)); return d;
}
// shifted softplus: max(x,0) + log(0.5 + 0.5*e^{-|x|})
__device__ __forceinline__ float sspf(float x) {
    float u = __expf(-fabsf(x));
    return fmaxf(x, 0.0f) + __logf(fmaf(0.5f, u, 0.5f));
}

// ---------------------------------------------------------------------------
// Edge pipeline: 512 threads, 128-edge tiles, persistent grid.
// Warp w owns edges e0=w*8..w*8+7.
//   L1 (N=128): lane owns j = 4L..4L+3 (j-pair f32x2 accumulation)
//   L2/L3/L4 (N=64): lane owns j = 2L..2L+1 (k-pair f32x2, transposed weights)
// ---------------------------------------------------------------------------
#define ESM_FLOATS 57920

__global__ void __launch_bounds__(512, 1)
edge_kernel(const float* __restrict__ edge_feats,
            const int* __restrict__ srcp, const int* __restrict__ dstp,
            const float* __restrict__ eu_w1, const float* __restrict__ eu_b1,
            const float* __restrict__ eu_w2, const float* __restrict__ eu_b2,
            const float* __restrict__ pe_w1, const float* __restrict__ pe_b1,
            const float* __restrict__ pe_w2, const float* __restrict__ pe_b2,
            float* __restrict__ agg, float* __restrict__ out_edge,
            int E, int numTiles) {
    extern __shared__ float sm[];
    float* sW1c  = sm;            // [64 k][128 j]   rbf rows of eu_w1
    float* sW2T  = sm + 8192;     // [64 j][128 k]   eu_w2 transposed
    float* sPe1T = sm + 16384;    // [64 j][64 k]
    float* sPe2T = sm + 20480;    // [64 j][64 k]
    float* sB1   = sm + 24576;    // 128
    float* sB2   = sm + 24704;    // 64
    float* sPb1  = sm + 24768;    // 64
    float* sPb2  = sm + 24832;    // 64
    int*   sIdx  = (int*)(sm + 24896); // src[128], dst[128]
    float* sX    = sm + 25152;    // [128 e][64 k]  (row-major rbf; reused as sT)
    float* sH1   = sm + 33344;    // [128 e][128 k]
    float* sNE   = sm + 49728;    // [128 e][64 k]
    float* sT    = sX;

    const int tid = threadIdx.x;
    for (int i = tid; i < 8192; i += 512)
        sW1c[i] = eu_w1[(128 + (i >> 7)) * 128 + (i & 127)];
    for (int i = tid; i < 8192; i += 512) {
        int k = i >> 6, j = i & 63; sW2T[j * 128 + k] = eu_w2[i];
    }
    for (int i = tid; i < 4096; i += 512) {
        int k = i >> 6, j = i & 63;
        sPe1T[j * 64 + k] = pe_w1[i];
        sPe2T[j * 64 + k] = pe_w2[i];
    }
    if (tid < 128) sB1[tid] = eu_b1[tid];
    if (tid < 64) { sB2[tid] = eu_b2[tid]; sPb1[tid] = pe_b1[tid]; sPb2[tid] = pe_b2[tid]; }
    __syncthreads();

    const int w = tid >> 5, L = tid & 31;
    const int e0 = w * 8;

    for (int tile = blockIdx.x; tile < numTiles; tile += gridDim.x) {
        const int base = tile * 128;
        if (tid < 128)       { int g = base + tid;       sIdx[tid] = (g < E) ? srcp[g] : 0; }
        else if (tid < 256)  { int g = base + tid - 128; sIdx[tid] = (g < E) ? dstp[g] : 0; }
        {   // linear row-major copy of the edge tile (no transpose, coalesced)
            const float4* g4 = (const float4*)(edge_feats) + (size_t)base * 16;
            float4* s4 = (float4*)sX;
#pragma unroll
            for (int i = tid; i < 2048; i += 512) {
                float4 v = make_float4(0.f, 0.f, 0.f, 0.f);
                if (base + (i >> 4) < E) v = g4[i];
                s4[i] = v;
            }
        }
        __syncthreads();

        // ---- L1: h1 = b1 + preA[src] + preB[dst] + rbf @ W1c ; sH1 = ssp(h1)
        {
            u64 acc[8][2];
            ulonglong2 bv = *(const ulonglong2*)(sB1 + 4 * L);
#pragma unroll
            for (int e = 0; e < 8; e++) { acc[e][0] = bv.x; acc[e][1] = bv.y; }
#pragma unroll 2
            for (int k0 = 0; k0 < 64; k0 += 4) {
                ulonglong2 w0 = *(const ulonglong2*)(sW1c + (k0 + 0) * 128 + 4 * L);
                ulonglong2 w1 = *(const ulonglong2*)(sW1c + (k0 + 1) * 128 + 4 * L);
                ulonglong2 w2 = *(const ulonglong2*)(sW1c + (k0 + 2) * 128 + 4 * L);
                ulonglong2 w3 = *(const ulonglong2*)(sW1c + (k0 + 3) * 128 + 4 * L);
#pragma unroll
                for (int e = 0; e < 8; e++) {
                    float4 xv = *(const float4*)(sX + (e0 + e) * 64 + k0);
                    u64 x0 = pack2(xv.x, xv.x);
                    acc[e][0] = ffma2(x0, w0.x, acc[e][0]);
                    acc[e][1] = ffma2(x0, w0.y, acc[e][1]);
                    u64 x1 = pack2(xv.y, xv.y);
                    acc[e][0] = ffma2(x1, w1.x, acc[e][0]);
                    acc[e][1] = ffma2(x1, w1.y, acc[e][1]);
                    u64 x2 = pack2(xv.z, xv.z);
                    acc[e][0] = ffma2(x2, w2.x, acc[e][0]);
                    acc[e][1] = ffma2(x2, w2.y, acc[e][1]);
                    u64 x3 = pack2(xv.w, xv.w);
                    acc[e][0] = ffma2(x3, w3.x, acc[e][0]);
                    acc[e][1] = ffma2(x3, w3.y, acc[e][1]);
                }
            }
#pragma unroll
            for (int e = 0; e < 8; e++) {
                int s = sIdx[e0 + e], d = sIdx[128 + e0 + e];
                float4 pa = *(const float4*)(g_pre_a + (size_t)s * 128 + 4 * L);
                float4 pb = *(const float4*)(g_pre_b + (size_t)d * 128 + 4 * L);
                float2 v0 = unpack2(acc[e][0]), v1 = unpack2(acc[e][1]);
                float4 h;
                h.x = sspf(v0.x + pa.x + pb.x);
                h.y = sspf(v0.y + pa.y + pb.y);
                h.z = sspf(v1.x + pa.z + pb.z);
                h.w = sspf(v1.y + pa.w + pb.w);
                *(float4*)(sH1 + (e0 + e) * 128 + 4 * L) = h;
            }
        }
        __syncthreads();

        // ---- L2: new_edge = ssp_h1 @ eu_w2 + b2  (k-pair, W transposed)
        {
            u64 a2[8][2];
#pragma unroll
            for (int e = 0; e < 8; e++) { a2[e][0] = 0; a2[e][1] = 0; }
            const float* wr0 = sW2T + (2 * L) * 128;
            const float* wr1 = wr0 + 128;
#pragma unroll 2
            for (int k0 = 0; k0 < 128; k0 += 4) {
                ulonglong2 wj0 = *(const ulonglong2*)(wr0 + k0);
                ulonglong2 wj1 = *(const ulonglong2*)(wr1 + k0);
#pragma unroll
                for (int e = 0; e < 8; e++) {
                    ulonglong2 xu = *(const ulonglong2*)(sH1 + (e0 + e) * 128 + k0);
                    a2[e][0] = ffma2(xu.x, wj0.x, a2[e][0]);
                    a2[e][0] = ffma2(xu.y, wj0.y, a2[e][0]);
                    a2[e][1] = ffma2(xu.x, wj1.x, a2[e][1]);
                    a2[e][1] = ffma2(xu.y, wj1.y, a2[e][1]);
                }
            }
            float b0 = sB2[2 * L], b1 = sB2[2 * L + 1];
#pragma unroll
            for (int e = 0; e < 8; e++) {
                float2 p0 = unpack2(a2[e][0]), p1 = unpack2(a2[e][1]);
                float2 ne = make_float2(p0.x + p0.y + b0, p1.x + p1.y + b1);
                *(float2*)(sNE + (e0 + e) * 64 + 2 * L) = ne;
                int g = base + e0 + e;
                if (g < E) *(float2*)(out_edge + (size_t)g * 64 + 2 * L) = ne;
            }
        }
        __syncthreads();

        // ---- L3: t = ssp(new_edge @ pe_w1 + pe_b1)
        {
            u64 a3[8][2];
#pragma unroll
            for (int e = 0; e < 8; e++) { a3[e][0] = 0; a3[e][1] = 0; }
            const float* wr0 = sPe1T + (2 * L) * 64;
            const float* wr1 = wr0 + 64;
#pragma unroll 2
            for (int k0 = 0; k0 < 64; k0 += 4) {
                ulonglong2 wj0 = *(const ulonglong2*)(wr0 + k0);
                ulonglong2 wj1 = *(const ulonglong2*)(wr1 + k0);
#pragma unroll
                for (int e = 0; e < 8; e++) {
                    ulonglong2 xu = *(const ulonglong2*)(sNE + (e0 + e) * 64 + k0);
                    a3[e][0] = ffma2(xu.x, wj0.x, a3[e][0]);
                    a3[e][0] = ffma2(xu.y, wj0.y, a3[e][0]);
                    a3[e][1] = ffma2(xu.x, wj1.x, a3[e][1]);
                    a3[e][1] = ffma2(xu.y, wj1.y, a3[e][1]);
                }
            }
            float b0 = sPb1[2 * L], b1 = sPb1[2 * L + 1];
#pragma unroll
            for (int e = 0; e < 8; e++) {
                float2 p0 = unpack2(a3[e][0]), p1 = unpack2(a3[e][1]);
                float2 t = make_float2(sspf(p0.x + p0.y + b0), sspf(p1.x + p1.y + b1));
                *(float2*)(sT + (e0 + e) * 64 + 2 * L) = t;
            }
        }
        __syncthreads();

        // ---- L4: he = t @ pe_w2 + pe_b2 ; atomic segment-sum at dst
        {
            u64 a4[8][2];
#pragma unroll
            for (int e = 0; e < 8; e++) { a4[e][0] = 0; a4[e][1] = 0; }
            const float* wr0 = sPe2T + (2 * L) * 64;
            const float* wr1 = wr0 + 64;
#pragma unroll 2
            for (int k0 = 0; k0 < 64; k0 += 4) {
                ulonglong2 wj0 = *(const ulonglong2*)(wr0 + k0);
                ulonglong2 wj1 = *(const ulonglong2*)(wr1 + k0);
#pragma unroll
                for (int e = 0; e < 8; e++) {
                    ulonglong2 xu = *(const ulonglong2*)(sT + (e0 + e) * 64 + k0);
                    a4[e][0] = ffma2(xu.x, wj0.x, a4[e][0]);
                    a4[e][0] = ffma2(xu.y, wj0.y, a4[e][0]);
                    a4[e][1] = ffma2(xu.x, wj1.x, a4[e][1]);
                    a4[e][1] = ffma2(xu.y, wj1.y, a4[e][1]);
                }
            }
            float b0 = sPb2[2 * L], b1 = sPb2[2 * L + 1];
#pragma unroll
            for (int e = 0; e < 8; e++) {
                int g = base + e0 + e;
                if (g < E) {
                    float2 p0 = unpack2(a4[e][0]), p1 = unpack2(a4[e][1]);
                    int d = sIdx[128 + e0 + e];
                    float* ap = agg + (size_t)d * 64 + 2 * L;
                    atomicAdd(ap,     p0.x + p0.y + b0);
                    atomicAdd(ap + 1, p1.x + p1.y + b1);
                }
            }
        }
        __syncthreads();   // before next tile overwrites sX/sNE/sH1/sIdx
    }
}

// ---------------------------------------------------------------------------
// node precompute: g_pre_{a,b}[n][0:128] = nf[n] @ eu_w1[half*64 : half*64+64]
// 512 thr, 128-node tiles; L1-style j-pair GEMM, N=128, K=64.
// ---------------------------------------------------------------------------
__global__ void __launch_bounds__(512, 1)
node_pre_kernel(const float* __restrict__ node_feats,
                const float* __restrict__ eu_w1, int N) {
    extern __shared__ float sm[];
    float* sW = sm;          // [64][128]
    float* sX = sm + 8192;   // [128 n][64 k]
    const int tid = threadIdx.x;
    const int half = blockIdx.y;
    for (int i = tid; i < 8192; i += 512)
        sW[i] = eu_w1[(half * 64 + (i >> 7)) * 128 + (i & 127)];
    const int base = blockIdx.x * 128;
    {
        const float4* g4 = (const float4*)(node_feats) + (size_t)base * 16;
        float4* s4 = (float4*)sX;
#pragma unroll
        for (int i = tid; i < 2048; i += 512) {
            float4 v = make_float4(0.f, 0.f, 0.f, 0.f);
            if (base + (i >> 4) < N) v = g4[i];
            s4[i] = v;
        }
    }
    __syncthreads();
    const int w = tid >> 5, L = tid & 31;
    const int n0 = w * 8;
    u64 acc[8][2];
#pragma unroll
    for (int e = 0; e < 8; e++) { acc[e][0] = 0; acc[e][1] = 0; }
#pragma unroll 2
    for (int k0 = 0; k0 < 64; k0 += 4) {
        ulonglong2 w0 = *(const ulonglong2*)(sW + (k0 + 0) * 128 + 4 * L);
        ulonglong2 w1 = *(const ulonglong2*)(sW + (k0 + 1) * 128 + 4 * L);
        ulonglong2 w2 = *(const ulonglong2*)(sW + (k0 + 2) * 128 + 4 * L);
        ulonglong2 w3 = *(const ulonglong2*)(sW + (k0 + 3) * 128 + 4 * L);
#pragma unroll
        for (int e = 0; e < 8; e++) {
            float4 xv = *(const float4*)(sX + (n0 + e) * 64 + k0);
            u64 x0 = pack2(xv.x, xv.x);
            acc[e][0] = ffma2(x0, w0.x, acc[e][0]);
            acc[e][1] = ffma2(x0, w0.y, acc[e][1]);
            u64 x1 = pack2(xv.y, xv.y);
            acc[e][0] = ffma2(x1, w1.x, acc[e][0]);
            acc[e][1] = ffma2(x1, w1.y, acc[e][1]);
            u64 x2 = pack2(xv.z, xv.z);
            acc[e][0] = ffma2(x2, w2.x, acc[e][0]);
            acc[e][1] = ffma2(x2, w2.y, acc[e][1]);
            u64 x3 = pack2(xv.w, xv.w);
            acc[e][0] = ffma2(x3, w3.x, acc[e][0]);
            acc[e][1] = ffma2(x3, w3.y, acc[e][1]);
        }
    }
    float* outp = half ? g_pre_b : g_pre_a;
#pragma unroll
    for (int e = 0; e < 8; e++) {
        int g = base + n0 + e;
        if (g < N) {
            float2 v0 = unpack2(acc[e][0]), v1 = unpack2(acc[e][1]);
            *(float4*)(outp + (size_t)g * 128 + 4 * L) = make_float4(v0.x, v0.y, v1.x, v1.y);
        }
    }
}

// ---------------------------------------------------------------------------
// node post: out = node_feats + ssp(agg@pn2_w1+b1)@pn2_w2 + b2  (in place on agg)
// ---------------------------------------------------------------------------
__global__ void __launch_bounds__(512, 1)
node_post_kernel(const float* __restrict__ node_feats,
                 const float* __restrict__ w1, const float* __restrict__ b1,
                 const float* __restrict__ w2, const float* __restrict__ b2,
                 float* __restrict__ node_out, int N) {
    extern __shared__ float sm[];
    float* sW1T = sm;            // [64 j][64 k]
    float* sW2T = sm + 4096;
    float* sB1  = sm + 8192;     // 64
    float* sB2  = sm + 8256;     // 64
    float* sX   = sm + 8320;     // [128 n][64 k]
    float* sT   = sm + 16512;    // [128 n][64 k]
    const int tid = threadIdx.x;
    for (int i = tid; i < 4096; i += 512) {
        int k = i >> 6, j = i & 63;
        sW1T[j * 64 + k] = w1[i];
        sW2T[j * 64 + k] = w2[i];
    }
    if (tid < 64) { sB1[tid] = b1[tid]; sB2[tid] = b2[tid]; }
    const int base = blockIdx.x * 128;
    {
        const float4* g4 = (const float4*)(node_out) + (size_t)base * 16;
        float4* s4 = (float4*)sX;
#pragma unroll
        for (int i = tid; i < 2048; i += 512) {
            float4 v = make_float4(0.f, 0.f, 0.f, 0.f);
            if (base + (i >> 4) < N) v = g4[i];
            s4[i] = v;
        }
    }
    __syncthreads();
    const int w = tid >> 5, L = tid & 31;
    const int n0 = w * 8;
    {
        u64 a1[8][2];
#pragma unroll
        for (int e = 0; e < 8; e++) { a1[e][0] = 0; a1[e][1] = 0; }
        const float* wr0 = sW1T + (2 * L) * 64;
        const float* wr1 = wr0 + 64;
#pragma unroll 2
        for (int k0 = 0; k0 < 64; k0 += 4) {
            ulonglong2 wj0 = *(const ulonglong2*)(wr0 + k0);
            ulonglong2 wj1 = *(const ulonglong2*)(wr1 + k0);
#pragma unroll
            for (int e = 0; e < 8; e++) {
                ulonglong2 xu = *(const ulonglong2*)(sX + (n0 + e) * 64 + k0);
                a1[e][0] = ffma2(xu.x, wj0.x, a1[e][0]);
                a1[e][0] = ffma2(xu.y, wj0.y, a1[e][0]);
                a1[e][1] = ffma2(xu.x, wj1.x, a1[e][1]);
                a1[e][1] = ffma2(xu.y, wj1.y, a1[e][1]);
            }
        }
        float c0 = sB1[2 * L], c1 = sB1[2 * L + 1];
#pragma unroll
        for (int e = 0; e < 8; e++) {
            float2 p0 = unpack2(a1[e][0]), p1 = unpack2(a1[e][1]);
            *(float2*)(sT + (n0 + e) * 64 + 2 * L) =
                make_float2(sspf(p0.x + p0.y + c0), sspf(p1.x + p1.y + c1));
        }
    }
    __syncthreads();
    {
        u64 a2[8][2];
#pragma unroll
        for (int e = 0; e < 8; e++) { a2[e][0] = 0; a2[e][1] = 0; }
        const float* wr0 = sW2T + (2 * L) * 64;
        const float* wr1 = wr0 + 64;
#pragma unroll 2
        for (int k0 = 0; k0 < 64; k0 += 4) {
            ulonglong2 wj0 = *(const ulonglong2*)(wr0 + k0);
            ulonglong2 wj1 = *(const ulonglong2*)(wr1 + k0);
#pragma unroll
            for (int e = 0; e < 8; e++) {
                ulonglong2 xu = *(const ulonglong2*)(sT + (n0 + e) * 64 + k0);
                a2[e][0] = ffma2(xu.x, wj0.x, a2[e][0]);
                a2[e][0] = ffma2(xu.y, wj0.y, a2[e][0]);
                a2[e][1] = ffma2(xu.x, wj1.x, a2[e][1]);
                a2[e][1] = ffma2(xu.y, wj1.y, a2[e][1]);
            }
        }
        float c0 = sB2[2 * L], c1 = sB2[2 * L + 1];
#pragma unroll
        for (int e = 0; e < 8; e++) {
            int g = base + n0 + e;
            if (g < N) {
                float2 nf = *(const float2*)(node_feats + (size_t)g * 64 + 2 * L);
                float2 p0 = unpack2(a2[e][0]), p1 = unpack2(a2[e][1]);
                *(float2*)(node_out + (size_t)g * 64 + 2 * L) =
                    make_float2(p0.x + p0.y + c0 + nf.x, p1.x + p1.y + c1 + nf.y);
            }
        }
    }
}

extern "C" void kernel_launch(void* const* d_in, const int* in_sizes, int n_in,
                              void* d_out, int out_size) {
    const float* node_feats = (const float*)d_in[0];
    const float* edge_feats = (const float*)d_in[1];
    const int*   src  = (const int*)d_in[2];
    const int*   dst  = (const int*)d_in[3];
    const float* eu_w1 = (const float*)d_in[4];
    const float* eu_b1 = (const float*)d_in[5];
    const float* eu_w2 = (const float*)d_in[6];
    const float* eu_b2 = (const float*)d_in[7];
    const float* pe_w1 = (const float*)d_in[10];
    const float* pe_b1 = (const float*)d_in[11];
    const float* pe_w2 = (const float*)d_in[12];
    const float* pe_b2 = (const float*)d_in[13];
    const float* pn2_w1 = (const float*)d_in[14];
    const float* pn2_b1 = (const float*)d_in[15];
    const float* pn2_w2 = (const float*)d_in[16];
    const float* pn2_b2 = (const float*)d_in[17];

    const int N = in_sizes[0] / 64;
    const int E = in_sizes[1] / 64;
    float* out_node = (float*)d_out;
    float* out_edge = out_node + (size_t)N * 64;

    cudaFuncSetAttribute(edge_kernel, cudaFuncAttributeMaxDynamicSharedMemorySize,
                         ESM_FLOATS * 4);
    cudaFuncSetAttribute(node_pre_kernel, cudaFuncAttributeMaxDynamicSharedMemorySize,
                         16384 * 4);
    cudaFuncSetAttribute(node_post_kernel, cudaFuncAttributeMaxDynamicSharedMemorySize,
                         24704 * 4);

    cudaMemsetAsync(out_node, 0, (size_t)N * 64 * sizeof(float));

    dim3 gpre((N + 127) / 128, 2);
    node_pre_kernel<<<gpre, 512, 16384 * 4>>>(node_feats, eu_w1, N);

    int sms = 0;
    cudaDeviceGetAttribute(&sms, cudaDevAttrMultiProcessorCount, 0);
    if (sms <= 0) sms = 148;
    int numTiles = (E + 127) / 128;
    int grid = (sms < numTiles) ? sms : numTiles;
    edge_kernel<<<grid, 512, ESM_FLOATS * 4>>>(
        edge_feats, src, dst, eu_w1, eu_b1, eu_w2, eu_b2,
        pe_w1, pe_b1, pe_w2, pe_b2, out_node, out_edge, E, numTiles);

    node_post_kernel<<<(N + 127) / 128, 512, 24704 * 4>>>(
        node_feats, pn2_w1, pn2_b1, pn2_w2, pn2_b2, out_node, N);
}

// round 4
// speedup vs baseline: 2.1576x; 2.1576x over previous
#include <cuda_runtime.h>

#define NCAP 100000
typedef unsigned long long u64;

// per-node precomputed partials of eu_w1 (src-half / dst-half)
__device__ float g_pre_a[(size_t)NCAP * 128];
__device__ float g_pre_b[(size_t)NCAP * 128];

__device__ __forceinline__ u64 pack2(float lo, float hi) {
    u64 r; asm("mov.b64 %0,{%1,%2};" : "=l"(r) : "f"(lo), "f"(hi)); return r;
}
__device__ __forceinline__ float2 unpack2(u64 v) {
    float2 f; asm("mov.b64 {%0,%1},%2;" : "=f"(f.x), "=f"(f.y) : "l"(v)); return f;
}
__device__ __forceinline__ u64 ffma2(u64 a, u64 b, u64 c) {
    u64 d; asm("fma.rn.f32x2 %0,%1,%2,%3;" : "=l"(d) : "l"(a), "l"(b), "l"(c)); return d;
}
// shifted softplus: max(x,0) + log(0.5 + 0.5*e^{-|x|})
__device__ __forceinline__ float sspf(float x) {
    float u = __expf(-fabsf(x));
    return fmaxf(x, 0.0f) + __logf(fmaf(0.5f, u, 0.5f));
}

// ---------------------------------------------------------------------------
// Edge pipeline: 512 threads, 128-edge tiles, persistent grid.
// Warp w owns edges e0=w*8..w*8+7 — ALL inter-layer tiles warp-private.
//   L1 (N=128): lane owns j=4L..4L+3 (j-pair f32x2)
//   L2/L3/L4 (N=64): lane owns j=L and j=L+32 (k-pair f32x2, transposed W)
// Transposed-W pitch 132 / 68 floats: rows 16B-aligned (132*4=33*16, 68*4=17*16)
// and lane word-offset ≡ 4L (mod 32) → LDS.128 phases tile all banks once.
// ---------------------------------------------------------------------------
#define P132 132
#define P68  68
// smem float offsets (all multiples of 4 → 16B-aligned)
#define O_W1C  0        // [64][128]        8192
#define O_W2T  8192     // [64][132]        8448
#define O_PE1T 16640    // [64][68]         4352
#define O_PE2T 20992    // [64][68]         4352
#define O_B1   25344    // 128
#define O_B2   25472    // 64
#define O_PB1  25536    // 64
#define O_PB2  25600    // 64
#define O_IDX  25664    // 256 ints
#define O_X    25920    // [128][64]  (alias: sT)   8192
#define O_H1   34112    // [128][128] (alias: sNE fronts) 16384
#define ESM_FLOATS 50496

__global__ void __launch_bounds__(512, 1)
edge_kernel(const float* __restrict__ edge_feats,
            const int* __restrict__ srcp, const int* __restrict__ dstp,
            const float* __restrict__ eu_w1, const float* __restrict__ eu_b1,
            const float* __restrict__ eu_w2, const float* __restrict__ eu_b2,
            const float* __restrict__ pe_w1, const float* __restrict__ pe_b1,
            const float* __restrict__ pe_w2, const float* __restrict__ pe_b2,
            float* __restrict__ agg, float* __restrict__ out_edge,
            int E, int numTiles) {
    extern __shared__ float sm[];
    float* sW1c  = sm + O_W1C;
    float* sW2T  = sm + O_W2T;
    float* sPe1T = sm + O_PE1T;
    float* sPe2T = sm + O_PE2T;
    float* sB1   = sm + O_B1;
    float* sB2   = sm + O_B2;
    float* sPb1  = sm + O_PB1;
    float* sPb2  = sm + O_PB2;
    int*   sIdx  = (int*)(sm + O_IDX);
    float* sX    = sm + O_X;      // rbf tile, row-major; reused as sT
    float* sH1   = sm + O_H1;     // ssp(h1); row fronts reused as sNE
    float* sT    = sX;

    const int tid = threadIdx.x;
    for (int i = tid; i < 8192; i += 512)
        sW1c[i] = eu_w1[(128 + (i >> 7)) * 128 + (i & 127)];
    for (int i = tid; i < 8192; i += 512) {
        int k = i >> 6, j = i & 63; sW2T[j * P132 + k] = eu_w2[i];
    }
    for (int i = tid; i < 4096; i += 512) {
        int k = i >> 6, j = i & 63;
        sPe1T[j * P68 + k] = pe_w1[i];
        sPe2T[j * P68 + k] = pe_w2[i];
    }
    if (tid < 128) sB1[tid] = eu_b1[tid];
    if (tid < 64) { sB2[tid] = eu_b2[tid]; sPb1[tid] = pe_b1[tid]; sPb2[tid] = pe_b2[tid]; }
    __syncthreads();

    const int w = tid >> 5, L = tid & 31;
    const int e0 = w * 8;

    for (int tile = blockIdx.x; tile < numTiles; tile += gridDim.x) {
        const int base = tile * 128;
        if (tid < 128)       { int g = base + tid;       sIdx[tid] = (g < E) ? srcp[g] : 0; }
        else if (tid < 256)  { int g = base + tid - 128; sIdx[tid] = (g < E) ? dstp[g] : 0; }
        {   // linear row-major copy of the edge tile (coalesced, no transpose)
            const float4* g4 = (const float4*)(edge_feats) + (size_t)base * 16;
            float4* s4 = (float4*)sX;
#pragma unroll
            for (int i = tid; i < 2048; i += 512) {
                float4 v = make_float4(0.f, 0.f, 0.f, 0.f);
                if (base + (i >> 4) < E) v = g4[i];
                s4[i] = v;
            }
        }
        __syncthreads();

        // ---- L1: h1 = b1 + preA[src] + preB[dst] + rbf @ W1c ; sH1 = ssp(h1)
        {
            u64 acc[8][2];
            ulonglong2 bv = *(const ulonglong2*)(sB1 + 4 * L);
#pragma unroll
            for (int e = 0; e < 8; e++) { acc[e][0] = bv.x; acc[e][1] = bv.y; }
#pragma unroll 4
            for (int k0 = 0; k0 < 64; k0 += 4) {
                ulonglong2 w0 = *(const ulonglong2*)(sW1c + (k0 + 0) * 128 + 4 * L);
                ulonglong2 w1 = *(const ulonglong2*)(sW1c + (k0 + 1) * 128 + 4 * L);
                ulonglong2 w2 = *(const ulonglong2*)(sW1c + (k0 + 2) * 128 + 4 * L);
                ulonglong2 w3 = *(const ulonglong2*)(sW1c + (k0 + 3) * 128 + 4 * L);
#pragma unroll
                for (int e = 0; e < 8; e++) {
                    float4 xv = *(const float4*)(sX + (e0 + e) * 64 + k0);
                    u64 x0 = pack2(xv.x, xv.x);
                    acc[e][0] = ffma2(x0, w0.x, acc[e][0]);
                    acc[e][1] = ffma2(x0, w0.y, acc[e][1]);
                    u64 x1 = pack2(xv.y, xv.y);
                    acc[e][0] = ffma2(x1, w1.x, acc[e][0]);
                    acc[e][1] = ffma2(x1, w1.y, acc[e][1]);
                    u64 x2 = pack2(xv.z, xv.z);
                    acc[e][0] = ffma2(x2, w2.x, acc[e][0]);
                    acc[e][1] = ffma2(x2, w2.y, acc[e][1]);
                    u64 x3 = pack2(xv.w, xv.w);
                    acc[e][0] = ffma2(x3, w3.x, acc[e][0]);
                    acc[e][1] = ffma2(x3, w3.y, acc[e][1]);
                }
            }
#pragma unroll
            for (int e = 0; e < 8; e++) {
                int s = sIdx[e0 + e], d = sIdx[128 + e0 + e];
                float4 pa = *(const float4*)(g_pre_a + (size_t)s * 128 + 4 * L);
                float4 pb = *(const float4*)(g_pre_b + (size_t)d * 128 + 4 * L);
                float2 v0 = unpack2(acc[e][0]), v1 = unpack2(acc[e][1]);
                float4 h;
                h.x = sspf(v0.x + pa.x + pb.x);
                h.y = sspf(v0.y + pa.y + pb.y);
                h.z = sspf(v1.x + pa.z + pb.z);
                h.w = sspf(v1.y + pa.w + pb.w);
                *(float4*)(sH1 + (e0 + e) * 128 + 4 * L) = h;
            }
        }
        // no barrier: sH1 rows are warp-private

        // ---- L2: new_edge = ssp_h1 @ eu_w2 + b2 (k-pair; lane cols L, L+32)
        {
            u64 a2[8][2];
#pragma unroll
            for (int e = 0; e < 8; e++) { a2[e][0] = 0; a2[e][1] = 0; }
            const float* wr0 = sW2T + L * P132;
            const float* wr1 = wr0 + 32 * P132;
#pragma unroll 4
            for (int k0 = 0; k0 < 128; k0 += 4) {
                ulonglong2 wj0 = *(const ulonglong2*)(wr0 + k0);
                ulonglong2 wj1 = *(const ulonglong2*)(wr1 + k0);
#pragma unroll
                for (int e = 0; e < 8; e++) {
                    ulonglong2 xu = *(const ulonglong2*)(sH1 + (e0 + e) * 128 + k0);
                    a2[e][0] = ffma2(xu.x, wj0.x, a2[e][0]);
                    a2[e][0] = ffma2(xu.y, wj0.y, a2[e][0]);
                    a2[e][1] = ffma2(xu.x, wj1.x, a2[e][1]);
                    a2[e][1] = ffma2(xu.y, wj1.y, a2[e][1]);
                }
            }
            float b0 = sB2[L], b1 = sB2[L + 32];
#pragma unroll
            for (int e = 0; e < 8; e++) {
                float2 p0 = unpack2(a2[e][0]), p1 = unpack2(a2[e][1]);
                float ne0 = p0.x + p0.y + b0;
                float ne1 = p1.x + p1.y + b1;
                // sNE alias: front 64 floats of sH1 row (k-reads of this row done)
                sH1[(e0 + e) * 128 + L]      = ne0;
                sH1[(e0 + e) * 128 + L + 32] = ne1;
                int g = base + e0 + e;
                if (g < E) {
                    out_edge[(size_t)g * 64 + L]      = ne0;
                    out_edge[(size_t)g * 64 + L + 32] = ne1;
                }
            }
        }

        // ---- L3: t = ssp(new_edge @ pe_w1 + pe_b1)   (reads sNE alias)
        {
            u64 a3[8][2];
#pragma unroll
            for (int e = 0; e < 8; e++) { a3[e][0] = 0; a3[e][1] = 0; }
            const float* wr0 = sPe1T + L * P68;
            const float* wr1 = wr0 + 32 * P68;
#pragma unroll 4
            for (int k0 = 0; k0 < 64; k0 += 4) {
                ulonglong2 wj0 = *(const ulonglong2*)(wr0 + k0);
                ulonglong2 wj1 = *(const ulonglong2*)(wr1 + k0);
#pragma unroll
                for (int e = 0; e < 8; e++) {
                    ulonglong2 xu = *(const ulonglong2*)(sH1 + (e0 + e) * 128 + k0);
                    a3[e][0] = ffma2(xu.x, wj0.x, a3[e][0]);
                    a3[e][0] = ffma2(xu.y, wj0.y, a3[e][0]);
                    a3[e][1] = ffma2(xu.x, wj1.x, a3[e][1]);
                    a3[e][1] = ffma2(xu.y, wj1.y, a3[e][1]);
                }
            }
            float b0 = sPb1[L], b1 = sPb1[L + 32];
#pragma unroll
            for (int e = 0; e < 8; e++) {
                float2 p0 = unpack2(a3[e][0]), p1 = unpack2(a3[e][1]);
                // sT aliases sX: this warp's sX rows fully consumed in L1
                sT[(e0 + e) * 64 + L]      = sspf(p0.x + p0.y + b0);
                sT[(e0 + e) * 64 + L + 32] = sspf(p1.x + p1.y + b1);
            }
        }

        // ---- L4: he = t @ pe_w2 + pe_b2 ; atomic segment-sum at dst
        {
            u64 a4[8][2];
#pragma unroll
            for (int e = 0; e < 8; e++) { a4[e][0] = 0; a4[e][1] = 0; }
            const float* wr0 = sPe2T + L * P68;
            const float* wr1 = wr0 + 32 * P68;
#pragma unroll 4
            for (int k0 = 0; k0 < 64; k0 += 4) {
                ulonglong2 wj0 = *(const ulonglong2*)(wr0 + k0);
                ulonglong2 wj1 = *(const ulonglong2*)(wr1 + k0);
#pragma unroll
                for (int e = 0; e < 8; e++) {
                    ulonglong2 xu = *(const ulonglong2*)(sT + (e0 + e) * 64 + k0);
                    a4[e][0] = ffma2(xu.x, wj0.x, a4[e][0]);
                    a4[e][0] = ffma2(xu.y, wj0.y, a4[e][0]);
                    a4[e][1] = ffma2(xu.x, wj1.x, a4[e][1]);
                    a4[e][1] = ffma2(xu.y, wj1.y, a4[e][1]);
                }
            }
            float b0 = sPb2[L], b1 = sPb2[L + 32];
#pragma unroll
            for (int e = 0; e < 8; e++) {
                int g = base + e0 + e;
                if (g < E) {
                    float2 p0 = unpack2(a4[e][0]), p1 = unpack2(a4[e][1]);
                    int d = sIdx[128 + e0 + e];
                    float* ap = agg + (size_t)d * 64;
                    atomicAdd(ap + L,      p0.x + p0.y + b0);
                    atomicAdd(ap + L + 32, p1.x + p1.y + b1);
                }
            }
        }
        __syncthreads();   // before next tile's cooperative overwrite of sX/sIdx
    }
}

// ---------------------------------------------------------------------------
// node precompute: g_pre_{a,b}[n][0:128] = nf[n] @ eu_w1[half*64 .. +64]
// ---------------------------------------------------------------------------
__global__ void __launch_bounds__(512, 1)
node_pre_kernel(const float* __restrict__ node_feats,
                const float* __restrict__ eu_w1, int N) {
    extern __shared__ float sm[];
    float* sW = sm;          // [64][128]
    float* sX = sm + 8192;   // [128 n][64 k]
    const int tid = threadIdx.x;
    const int half = blockIdx.y;
    for (int i = tid; i < 8192; i += 512)
        sW[i] = eu_w1[(half * 64 + (i >> 7)) * 128 + (i & 127)];
    const int base = blockIdx.x * 128;
    {
        const float4* g4 = (const float4*)(node_feats) + (size_t)base * 16;
        float4* s4 = (float4*)sX;
#pragma unroll
        for (int i = tid; i < 2048; i += 512) {
            float4 v = make_float4(0.f, 0.f, 0.f, 0.f);
            if (base + (i >> 4) < N) v = g4[i];
            s4[i] = v;
        }
    }
    __syncthreads();
    const int w = tid >> 5, L = tid & 31;
    const int n0 = w * 8;
    u64 acc[8][2];
#pragma unroll
    for (int e = 0; e < 8; e++) { acc[e][0] = 0; acc[e][1] = 0; }
#pragma unroll 4
    for (int k0 = 0; k0 < 64; k0 += 4) {
        ulonglong2 w0 = *(const ulonglong2*)(sW + (k0 + 0) * 128 + 4 * L);
        ulonglong2 w1 = *(const ulonglong2*)(sW + (k0 + 1) * 128 + 4 * L);
        ulonglong2 w2 = *(const ulonglong2*)(sW + (k0 + 2) * 128 + 4 * L);
        ulonglong2 w3 = *(const ulonglong2*)(sW + (k0 + 3) * 128 + 4 * L);
#pragma unroll
        for (int e = 0; e < 8; e++) {
            float4 xv = *(const float4*)(sX + (n0 + e) * 64 + k0);
            u64 x0 = pack2(xv.x, xv.x);
            acc[e][0] = ffma2(x0, w0.x, acc[e][0]);
            acc[e][1] = ffma2(x0, w0.y, acc[e][1]);
            u64 x1 = pack2(xv.y, xv.y);
            acc[e][0] = ffma2(x1, w1.x, acc[e][0]);
            acc[e][1] = ffma2(x1, w1.y, acc[e][1]);
            u64 x2 = pack2(xv.z, xv.z);
            acc[e][0] = ffma2(x2, w2.x, acc[e][0]);
            acc[e][1] = ffma2(x2, w2.y, acc[e][1]);
            u64 x3 = pack2(xv.w, xv.w);
            acc[e][0] = ffma2(x3, w3.x, acc[e][0]);
            acc[e][1] = ffma2(x3, w3.y, acc[e][1]);
        }
    }
    float* outp = half ? g_pre_b : g_pre_a;
#pragma unroll
    for (int e = 0; e < 8; e++) {
        int g = base + n0 + e;
        if (g < N) {
            float2 v0 = unpack2(acc[e][0]), v1 = unpack2(acc[e][1]);
            *(float4*)(outp + (size_t)g * 128 + 4 * L) = make_float4(v0.x, v0.y, v1.x, v1.y);
        }
    }
}

// ---------------------------------------------------------------------------
// node post: out = node_feats + ssp(agg@pn2_w1+b1)@pn2_w2 + b2 (in place)
// ---------------------------------------------------------------------------
__global__ void __launch_bounds__(512, 1)
node_post_kernel(const float* __restrict__ node_feats,
                 const float* __restrict__ w1, const float* __restrict__ b1,
                 const float* __restrict__ w2, const float* __restrict__ b2,
                 float* __restrict__ node_out, int N) {
    extern __shared__ float sm[];
    float* sW1T = sm;            // [64 j][68]
    float* sW2T = sm + 4352;
    float* sB1  = sm + 8704;     // 64
    float* sB2  = sm + 8768;     // 64
    float* sX   = sm + 8832;     // [128 n][64]
    float* sT   = sm + 17024;    // [128 n][64]
    const int tid = threadIdx.x;
    for (int i = tid; i < 4096; i += 512) {
        int k = i >> 6, j = i & 63;
        sW1T[j * P68 + k] = w1[i];
        sW2T[j * P68 + k] = w2[i];
    }
    if (tid < 64) { sB1[tid] = b1[tid]; sB2[tid] = b2[tid]; }
    const int base = blockIdx.x * 128;
    {
        const float4* g4 = (const float4*)(node_out) + (size_t)base * 16;
        float4* s4 = (float4*)sX;
#pragma unroll
        for (int i = tid; i < 2048; i += 512) {
            float4 v = make_float4(0.f, 0.f, 0.f, 0.f);
            if (base + (i >> 4) < N) v = g4[i];
            s4[i] = v;
        }
    }
    __syncthreads();
    const int w = tid >> 5, L = tid & 31;
    const int n0 = w * 8;
    {
        u64 a1[8][2];
#pragma unroll
        for (int e = 0; e < 8; e++) { a1[e][0] = 0; a1[e][1] = 0; }
        const float* wr0 = sW1T + L * P68;
        const float* wr1 = wr0 + 32 * P68;
#pragma unroll 4
        for (int k0 = 0; k0 < 64; k0 += 4) {
            ulonglong2 wj0 = *(const ulonglong2*)(wr0 + k0);
            ulonglong2 wj1 = *(const ulonglong2*)(wr1 + k0);
#pragma unroll
            for (int e = 0; e < 8; e++) {
                ulonglong2 xu = *(const ulonglong2*)(sX + (n0 + e) * 64 + k0);
                a1[e][0] = ffma2(xu.x, wj0.x, a1[e][0]);
                a1[e][0] = ffma2(xu.y, wj0.y, a1[e][0]);
                a1[e][1] = ffma2(xu.x, wj1.x, a1[e][1]);
                a1[e][1] = ffma2(xu.y, wj1.y, a1[e][1]);
            }
        }
        float c0 = sB1[L], c1 = sB1[L + 32];
#pragma unroll
        for (int e = 0; e < 8; e++) {
            float2 p0 = unpack2(a1[e][0]), p1 = unpack2(a1[e][1]);
            sT[(n0 + e) * 64 + L]      = sspf(p0.x + p0.y + c0);
            sT[(n0 + e) * 64 + L + 32] = sspf(p1.x + p1.y + c1);
        }
    }
    // no barrier: sT rows are warp-private
    {
        u64 a2[8][2];
#pragma unroll
        for (int e = 0; e < 8; e++) { a2[e][0] = 0; a2[e][1] = 0; }
        const float* wr0 = sW2T + L * P68;
        const float* wr1 = wr0 + 32 * P68;
#pragma unroll 4
        for (int k0 = 0; k0 < 64; k0 += 4) {
            ulonglong2 wj0 = *(const ulonglong2*)(wr0 + k0);
            ulonglong2 wj1 = *(const ulonglong2*)(wr1 + k0);
#pragma unroll
            for (int e = 0; e < 8; e++) {
                ulonglong2 xu = *(const ulonglong2*)(sT + (n0 + e) * 64 + k0);
                a2[e][0] = ffma2(xu.x, wj0.x, a2[e][0]);
                a2[e][0] = ffma2(xu.y, wj0.y, a2[e][0]);
                a2[e][1] = ffma2(xu.x, wj1.x, a2[e][1]);
                a2[e][1] = ffma2(xu.y, wj1.y, a2[e][1]);
            }
        }
        float c0 = sB2[L], c1 = sB2[L + 32];
#pragma unroll
        for (int e = 0; e < 8; e++) {
            int g = base + n0 + e;
            if (g < N) {
                float nf0 = node_feats[(size_t)g * 64 + L];
                float nf1 = node_feats[(size_t)g * 64 + L + 32];
                float2 p0 = unpack2(a2[e][0]), p1 = unpack2(a2[e][1]);
                node_out[(size_t)g * 64 + L]      = p0.x + p0.y + c0 + nf0;
                node_out[(size_t)g * 64 + L + 32] = p1.x + p1.y + c1 + nf1;
            }
        }
    }
}

extern "C" void kernel_launch(void* const* d_in, const int* in_sizes, int n_in,
                              void* d_out, int out_size) {
    const float* node_feats = (const float*)d_in[0];
    const float* edge_feats = (const float*)d_in[1];
    const int*   src  = (const int*)d_in[2];
    const int*   dst  = (const int*)d_in[3];
    const float* eu_w1 = (const float*)d_in[4];
    const float* eu_b1 = (const float*)d_in[5];
    const float* eu_w2 = (const float*)d_in[6];
    const float* eu_b2 = (const float*)d_in[7];
    const float* pe_w1 = (const float*)d_in[10];
    const float* pe_b1 = (const float*)d_in[11];
    const float* pe_w2 = (const float*)d_in[12];
    const float* pe_b2 = (const float*)d_in[13];
    const float* pn2_w1 = (const float*)d_in[14];
    const float* pn2_b1 = (const float*)d_in[15];
    const float* pn2_w2 = (const float*)d_in[16];
    const float* pn2_b2 = (const float*)d_in[17];

    const int N = in_sizes[0] / 64;
    const int E = in_sizes[1] / 64;
    float* out_node = (float*)d_out;
    float* out_edge = out_node + (size_t)N * 64;

    cudaFuncSetAttribute(edge_kernel, cudaFuncAttributeMaxDynamicSharedMemorySize,
                         ESM_FLOATS * 4);
    cudaFuncSetAttribute(node_pre_kernel, cudaFuncAttributeMaxDynamicSharedMemorySize,
                         16384 * 4);
    cudaFuncSetAttribute(node_post_kernel, cudaFuncAttributeMaxDynamicSharedMemorySize,
                         25216 * 4);

    cudaMemsetAsync(out_node, 0, (size_t)N * 64 * sizeof(float));

    dim3 gpre((N + 127) / 128, 2);
    node_pre_kernel<<<gpre, 512, 16384 * 4>>>(node_feats, eu_w1, N);

    int sms = 0;
    cudaDeviceGetAttribute(&sms, cudaDevAttrMultiProcessorCount, 0);
    if (sms <= 0) sms = 148;
    int numTiles = (E + 127) / 128;
    int grid = (sms < numTiles) ? sms : numTiles;
    edge_kernel<<<grid, 512, ESM_FLOATS * 4>>>(
        edge_feats, src, dst, eu_w1, eu_b1, eu_w2, eu_b2,
        pe_w1, pe_b1, pe_w2, pe_b2, out_node, out_edge, E, numTiles);

    node_post_kernel<<<(N + 127) / 128, 512, 25216 * 4>>>(
        node_feats, pn2_w1, pn2_b1, pn2_w2, pn2_b2, out_node, N);
}